// round 13
// baseline (speedup 1.0000x reference)
#include <cuda_runtime.h>
#include <cstdint>

// Problem constants (fixed by the reference)
#define N_TOKENS  131072
#define HIDDEN    2048
#define N_RANKS   8
#define N_EXPERTS 16
#define NSEG (N_RANKS * N_EXPERTS)   // 128
#define VEC_PER_ROW (HIDDEN / 4)     // 512 float4

// d_out float layout:
//   [0, N_TOKENS*HIDDEN)   permute_tokens
//   [+N_TOKENS)            permute_per_token_scales
//   [+N_TOKENS)            idx (as float, exact: < 2^24)
//   [+N_EXPERTS)           expert_token_num (as float)
#define OFF_SCALES ((size_t)N_TOKENS * HIDDEN)
#define OFF_IDX    (OFF_SCALES + N_TOKENS)
#define OFF_ETN    (OFF_IDX + N_TOKENS)

#define FULLMASK 0xffffffffu

__device__ __forceinline__ int warp_exscan(int v, int lane) {
    int inc = v;
    #pragma unroll
    for (int o = 1; o < 32; o <<= 1) {
        int n = __shfl_up_sync(FULLMASK, inc, o);
        if (lane >= o) inc += n;
    }
    return inc - v;   // exclusive
}

// ---------------------------------------------------------------------------
// Fully barrier-free, smem-free fused kernel: 65536 blocks x 256 threads,
// 2 rows per block. EVERY warp independently builds both 128-entry exclusive
// prefix tables in registers (4 entries/lane + shfl exscan), then resolves
// each of the block's 2 rows with a ballot+clz+shfl register search.
// No __syncthreads, no shared memory, no LDS chains — each warp's token
// loads issue as soon as its own register chain resolves.
// ---------------------------------------------------------------------------
__global__ void __launch_bounds__(256, 8)
k_fused(const float4* __restrict__ tokens,
        const int*    __restrict__ counts,
        const float*  __restrict__ scales,
        float*        __restrict__ out) {
    const int t = threadIdx.x;
    const int lane = t & 31;
    float4* __restrict__ out4 = (float4*)out;

    // ---- per-warp register tables -------------------------------------
    const int base = lane * 4;
    // table A: input order (flat r*E+e) — contiguous, one LDG.128
    const int4 av = __ldg((const int4*)(counts + base));
    // table B: output order s = e*R+r  ->  count index (s&7)*E + (s>>3)
    const int b0 = __ldg(&counts[((base + 0) & 7) * N_EXPERTS + ((base + 0) >> 3)]);
    const int b1 = __ldg(&counts[((base + 1) & 7) * N_EXPERTS + ((base + 1) >> 3)]);
    const int b2 = __ldg(&counts[((base + 2) & 7) * N_EXPERTS + ((base + 2) >> 3)]);
    const int b3 = __ldg(&counts[((base + 3) & 7) * N_EXPERTS + ((base + 3) >> 3)]);

    const int exA = warp_exscan(av.x + av.y + av.z + av.w, lane);
    const int exB = warp_exscan(b0 + b1 + b2 + b3, lane);

    // lane-local exclusive starts for entries base..base+3
    const int a0 = exA;
    const int a1 = exA + av.x;
    const int a2 = a1 + av.y;
    const int a3 = a2 + av.z;
    const int s0 = exB;
    const int s1 = exB + b0;
    const int s2 = s1 + b1;
    const int s3 = s2 + b2;

    // expert_token_num[e] = sum_r counts[r][e]  (block 0, lanes of warp 1)
    if (blockIdx.x == 0 && t >= 32 && t < 32 + N_EXPERTS) {
        const int e = t - 32;
        int sum = 0;
        #pragma unroll
        for (int r = 0; r < N_RANKS; ++r) sum += __ldg(&counts[r * N_EXPERTS + e]);
        out[OFF_ETN + e] = (float)sum;
    }

    // ---- register search for the block's two rows ---------------------
    const int row0 = blockIdx.x * 2;
    int src[2];
    #pragma unroll
    for (int k = 0; k < 2; ++k) {
        const int row = row0 + k;
        // which lane owns the containing segment group? (lane 0 has exB=0)
        const unsigned m = __ballot_sync(FULLMASK, exB <= row);
        const int L = 31 - __clz(m);
        const int t0 = __shfl_sync(FULLMASK, s0, L);
        const int t1 = __shfl_sync(FULLMASK, s1, L);
        const int t2 = __shfl_sync(FULLMASK, s2, L);
        const int t3 = __shfl_sync(FULLMASK, s3, L);
        const int j  = (t1 <= row) + (t2 <= row) + (t3 <= row);
        const int lo = L * 4 + j;                         // output segment e*R+r
        const int start = (j == 0) ? t0 : (j == 1) ? t1 : (j == 2) ? t2 : t3;
        // input-order segment index: r*E + e
        const int seg = (lo & 7) * N_EXPERTS + (lo >> 3);
        const int Ls = seg >> 2, js = seg & 3;
        const int u0 = __shfl_sync(FULLMASK, a0, Ls);
        const int u1 = __shfl_sync(FULLMASK, a1, Ls);
        const int u2 = __shfl_sync(FULLMASK, a2, Ls);
        const int u3 = __shfl_sync(FULLMASK, a3, Ls);
        const int in_start = (js == 0) ? u0 : (js == 1) ? u1 : (js == 2) ? u2 : u3;
        src[k] = in_start + (row - start);
    }

    const float4* __restrict__ in0 = tokens + (size_t)src[0] * VEC_PER_ROW;
    const float4* __restrict__ in1 = tokens + (size_t)src[1] * VEC_PER_ROW;
    float4* __restrict__ o0 = out4 + (size_t)row0 * VEC_PER_ROW;
    float4* __restrict__ o1 = o0 + VEC_PER_ROW;

    // 4 independent front-batched streaming loads (read-once).
    float4 a = __ldcs(&in0[t]);
    float4 b = __ldcs(&in0[t + 256]);
    float4 c = __ldcs(&in1[t]);
    float4 d = __ldcs(&in1[t + 256]);

    // Scale + idx inline (threads 0/1, one row each).
    if (t < 2) {
        const int row = row0 + t;
        const int s   = src[t];
        out[OFF_SCALES + row] = __ldg(&scales[s]);
        out[OFF_IDX + row]    = (float)s;
    }

    // Streaming stores (write-once, never re-read).
    __stcs(&o0[t],       a);
    __stcs(&o0[t + 256], b);
    __stcs(&o1[t],       c);
    __stcs(&o1[t + 256], d);
}

// ---------------------------------------------------------------------------
extern "C" void kernel_launch(void* const* d_in, const int* in_sizes, int n_in,
                              void* d_out, int out_size) {
    const float* tokens = (const float*)d_in[0];
    const int*   counts = (const int*)d_in[1];     // [N_RANKS, N_EXPERTS]
    const float* scales = (const float*)d_in[2];
    // d_in[3] = expert_token_num_type (1), d_in[4] = idx_type (0) — fixed.
    float* out = (float*)d_out;

    k_fused<<<N_TOKENS / 2, 256>>>((const float4*)tokens, counts, scales, out);
}